// round 14
// baseline (speedup 1.0000x reference)
#include <cuda_runtime.h>
#include <cstdint>

// PointMaxPool fused pipeline, r14: FPS body reverted byte-exact to the
// proven Round-8 version (1073.5us, rel_err 0.0); gather epilogue x4-vectorized.
#define N_PTS    8192
#define N_SMP    2048
#define BATCH    8
#define CHANNELS 128

// KNN decomposition inside the fused kernel
#define KNN_CTAS_PER_BATCH 32          // 256 queries per CTA
#define KNN_Q_PER_CTA      256
#define CHUNK_PTS          4096

// force 1 CTA/SM (2 x 116KB > 227KB): FPS CTAs never share an SM with KNN
#define FUSED_SMEM_BYTES   (116 * 1024)

// device-global scratch (sanctioned workaround for no-malloc rule)
__device__ int   g_idx[BATCH * N_SMP];                          // FPS sample indices
__device__ float g_allpooled[(size_t)BATCH * CHANNELS * N_PTS]; // pooled feats, ALL points

// ---- packed f32x2 helpers (two independent rn-rounded f32 ops per instr).
// Fallback is two scalar rn ops: bit-identical either way. ----
#if defined(__CUDA_ARCH__) && (__CUDA_ARCH__ >= 1000)
#define HAS_F32X2 1
#else
#define HAS_F32X2 0
#endif

struct P2 { float lo, hi; };

__device__ __forceinline__ P2 pk2(float a, float b) { P2 r; r.lo = a; r.hi = b; return r; }

__device__ __forceinline__ P2 add2(P2 a, P2 b) {
#if HAS_F32X2
    unsigned long long av, bv, rv;
    asm("mov.b64 %0, {%1, %2};" : "=l"(av) : "f"(a.lo), "f"(a.hi));
    asm("mov.b64 %0, {%1, %2};" : "=l"(bv) : "f"(b.lo), "f"(b.hi));
    asm("add.rn.f32x2 %0, %1, %2;" : "=l"(rv) : "l"(av), "l"(bv));
    P2 r;
    asm("mov.b64 {%0, %1}, %2;" : "=f"(r.lo), "=f"(r.hi) : "l"(rv));
    return r;
#else
    P2 r; r.lo = __fadd_rn(a.lo, b.lo); r.hi = __fadd_rn(a.hi, b.hi); return r;
#endif
}

__device__ __forceinline__ P2 sub2(P2 a, P2 b) {
#if HAS_F32X2
    unsigned long long av, bv, rv;
    asm("mov.b64 %0, {%1, %2};" : "=l"(av) : "f"(a.lo), "f"(a.hi));
    asm("mov.b64 %0, {%1, %2};" : "=l"(bv) : "f"(b.lo), "f"(b.hi));
    asm("sub.rn.f32x2 %0, %1, %2;" : "=l"(rv) : "l"(av), "l"(bv));
    P2 r;
    asm("mov.b64 {%0, %1}, %2;" : "=f"(r.lo), "=f"(r.hi) : "l"(rv));
    return r;
#else
    P2 r; r.lo = __fsub_rn(a.lo, b.lo); r.hi = __fsub_rn(a.hi, b.hi); return r;
#endif
}

__device__ __forceinline__ P2 mul2(P2 a, P2 b) {
#if HAS_F32X2
    unsigned long long av, bv, rv;
    asm("mov.b64 %0, {%1, %2};" : "=l"(av) : "f"(a.lo), "f"(a.hi));
    asm("mov.b64 %0, {%1, %2};" : "=l"(bv) : "f"(b.lo), "f"(b.hi));
    asm("mul.rn.f32x2 %0, %1, %2;" : "=l"(rv) : "l"(av), "l"(bv));
    P2 r;
    asm("mov.b64 {%0, %1}, %2;" : "=f"(r.lo), "=f"(r.hi) : "l"(rv));
    return r;
#else
    P2 r; r.lo = __fmul_rn(a.lo, b.lo); r.hi = __fmul_rn(a.hi, b.hi); return r;
#endif
}

// ---------------------------------------------------------------------------
// FPS body: single CTA (1024 threads) per batch, bit-exact selection.
// (Round-8 proven version, reverted verbatim.) Per iteration:
// packed sub2/mul2/add2 distance update with IN-LOOP (bestb,bidx) tracking
// (ALU-pipe ops, overlapped under the issue budget), warp REDUX pair,
// u64 STS (double-buffered), one BAR, then every warp LDS.64 + dual REDUX
// over the 32 candidates. dist >= 0 so float bits order as u32; strict '>'
// in ascending slot order keeps first occurrence (jnp.argmax semantics).
// ---------------------------------------------------------------------------
__device__ void fps_body(const float* __restrict__ pos, char* smem, int b)
{
    float2* xy = (float2*)smem;                    // [8192]  64 KB
    float*  zs = (float*)(smem + N_PTS * 8);       // [8192]  32 KB
    __shared__ unsigned long long s_cand[2][32];   // (valbits<<32)|idx

    const int t = threadIdx.x;
    const int lane = t & 31;
    const int warp = t >> 5;
    const float* p = pos + (size_t)b * 3 * N_PTS;

    // slot s owns point j = t + s*1024; pair q packs slots (2q, 2q+1)
    P2 x2[4], y2[4], z2[4];
    float dist[8];
    {
        float xv[8], yv[8], zv[8];
#pragma unroll
        for (int s = 0; s < 8; s++) {
            int j = t + (s << 10);
            xv[s] = p[j];
            yv[s] = p[N_PTS + j];
            zv[s] = p[2 * N_PTS + j];
            xy[j] = make_float2(xv[s], yv[s]);
            zs[j] = zv[s];
            dist[s] = 1e10f;   // reference init 10000000000.0
        }
#pragma unroll
        for (int q = 0; q < 4; q++) {
            x2[q] = pk2(xv[2 * q], xv[2 * q + 1]);
            y2[q] = pk2(yv[2 * q], yv[2 * q + 1]);
            z2[q] = pk2(zv[2 * q], zv[2 * q + 1]);
        }
    }
    __syncthreads();

    int far = 0;
    int buf = 0;
    int* idxout = g_idx + b * N_SMP;

    for (int m = 0; m < N_SMP; m++) {
        float2 cxy = xy[far];
        float  cz  = zs[far];
        if (t == 0) idxout[m] = far;   // scan emits `farthest` at step entry
        P2 cxx = pk2(cxy.x, cxy.x);
        P2 cyy = pk2(cxy.y, cxy.y);
        P2 czz = pk2(cz, cz);

        // packed distance update + in-loop argmax tracking
        unsigned bestb = 0u;
        int bidx = t;
#pragma unroll
        for (int q = 0; q < 4; q++) {
            P2 dx = sub2(x2[q], cxx);
            P2 dy = sub2(y2[q], cyy);
            P2 dz = sub2(z2[q], czz);
            P2 xx = mul2(dx, dx);
            P2 yy = mul2(dy, dy);
            P2 zz = mul2(dz, dz);
            P2 d2 = add2(add2(xx, yy), zz);   // ((xx+yy)+zz), each rn
            float nlo = fminf(dist[2 * q],     d2.lo);
            float nhi = fminf(dist[2 * q + 1], d2.hi);
            dist[2 * q]     = nlo;
            dist[2 * q + 1] = nhi;
            unsigned blo = __float_as_uint(nlo);
            if (blo > bestb) { bestb = blo; bidx = t + (q << 11); }
            unsigned bhi = __float_as_uint(nhi);
            if (bhi > bestb) { bestb = bhi; bidx = t + (q << 11) + 1024; }
        }

        // warp argmax via REDUX: max value bits, min idx among matches
        unsigned wmax = __reduce_max_sync(0xffffffffu, bestb);
        unsigned cand = (bestb == wmax) ? (unsigned)bidx : 0xffffffffu;
        unsigned widx = __reduce_min_sync(0xffffffffu, cand);

        if (lane == 0)
            s_cand[buf][warp] = ((unsigned long long)wmax << 32) | widx;
        __syncthreads();

        // every warp redundantly combines the 32 candidates (double-buffered)
        unsigned long long c64 = s_cand[buf][lane];
        unsigned v = (unsigned)(c64 >> 32);
        unsigned i = (unsigned)c64;
        unsigned gmax = __reduce_max_sync(0xffffffffu, v);
        unsigned gc   = (v == gmax) ? i : 0xffffffffu;
        far = (int)__reduce_min_sync(0xffffffffu, gc);
        buf ^= 1;
    }
}

// ---------------------------------------------------------------------------
// All-pairs KNN body: 4-NN + channel max-pool for EVERY input point
// (sampled queries are input points, so query m's row == point idx[m]'s row
// under the reference's own dist formula). Unchanged from Rounds 7/8.
// ---------------------------------------------------------------------------
__device__ void allknn_body(const float* __restrict__ feats,
                            const float* __restrict__ pos,
                            char* smem, int cta)
{
    float4* tile = (float4*)smem;      // [4096] = 64 KB of the alloc

    const int b    = cta / KNN_CTAS_PER_BATCH;
    const int qblk = cta % KNN_CTAS_PER_BATCH;
    const int t    = threadIdx.x;
    const int part = t & 3;
    const int q    = qblk * KNN_Q_PER_CTA + (t >> 2);   // 0..8191

    const float* p = pos + (size_t)b * 3 * N_PTS;
    float sx = p[q];
    float sy = p[N_PTS + q];
    float sz = p[2 * N_PTS + q];
    float s2 = __fadd_rn(__fadd_rn(__fmul_rn(sx, sx), __fmul_rn(sy, sy)),
                         __fmul_rn(sz, sz));

    const float INF = __int_as_float(0x7f800000);
    float d0 = INF, d1 = INF, d2 = INF, d3 = INF;
    int   i0 = 0x7fffffff, i1 = 0x7fffffff, i2 = 0x7fffffff, i3 = 0x7fffffff;

    for (int chunk = 0; chunk < N_PTS / CHUNK_PTS; chunk++) {
        const int base = chunk * CHUNK_PTS;
        __syncthreads();   // previous chunk fully consumed before overwrite
        for (int j = t; j < CHUNK_PTS; j += 1024) {
            int g = base + j;
            float px = p[g];
            float py = p[N_PTS + g];
            float pz = p[2 * N_PTS + g];
            float p2 = __fadd_rn(__fadd_rn(__fmul_rn(px, px), __fmul_rn(py, py)),
                                 __fmul_rn(pz, pz));
            tile[j] = make_float4(px, py, pz, p2);
        }
        __syncthreads();

        // ascending global idx within a part -> '<' keeps first occurrence
#pragma unroll 4
        for (int i = 0; i < CHUNK_PTS / 4; i++) {
            int e = (i << 2) + part;
            float4 pt = tile[e];
            float cross = __fadd_rn(__fadd_rn(__fmul_rn(sx, pt.x), __fmul_rn(sy, pt.y)),
                                    __fmul_rn(sz, pt.z));
            float dv = __fsub_rn(__fadd_rn(s2, pt.w), __fmul_rn(2.0f, cross));
            if (dv < d3) {
                int j = base + e;
                if (dv < d2) {
                    d3 = d2; i3 = i2;
                    if (dv < d1) {
                        d2 = d1; i2 = i1;
                        if (dv < d0) { d1 = d0; i1 = i0; d0 = dv; i0 = j; }
                        else         { d1 = dv; i1 = j; }
                    } else { d2 = dv; i2 = j; }
                } else { d3 = dv; i3 = j; }
            }
        }
    }

    // merge 4 per-part sorted lists: 4 rounds of (d, idx)-lexicographic min
    int mi[4];
#pragma unroll
    for (int r = 0; r < 4; r++) {
        float hd = d0;
        int   hi = i0;
#pragma unroll
        for (int off = 1; off < 4; off <<= 1) {
            float od = __shfl_xor_sync(0xffffffffu, hd, off, 4);
            int   oi = __shfl_xor_sync(0xffffffffu, hi, off, 4);
            if (od < hd || (od == hd && oi < hi)) { hd = od; hi = oi; }
        }
        mi[r] = hi;
        if (hi == i0) {   // global indices unique -> exact pop test
            d0 = d1; i0 = i1;
            d1 = d2; i1 = i2;
            d2 = d3; i2 = i3;
            d3 = INF; i3 = 0x7fffffff;
        }
    }

    // each part max-pools its own 32 channels into the all-points buffer
    const float* f0 = feats + (size_t)b * CHANNELS * N_PTS;
    float* gp = g_allpooled + (size_t)b * CHANNELS * N_PTS + q;
#pragma unroll 4
    for (int cc = 0; cc < CHANNELS / 4; cc++) {
        int c = part * (CHANNELS / 4) + cc;
        const float* fc = f0 + (size_t)c * N_PTS;
        float v = fmaxf(fmaxf(__ldg(fc + mi[0]), __ldg(fc + mi[1])),
                        fmaxf(__ldg(fc + mi[2]), __ldg(fc + mi[3])));
        gp[(size_t)c * N_PTS] = v;
    }
}

// ---------------------------------------------------------------------------
// Fused kernel: bids 0..7 = FPS (one per batch); bids 8..263 = all-pairs
// KNN (concurrent on the other SMs, finishes well inside the FPS window).
// 116 KB dynamic smem forces 1 CTA/SM -> FPS never shares an SM with KNN.
// ---------------------------------------------------------------------------
__global__ void __launch_bounds__(1024, 1)
fused_kernel(const float* __restrict__ feats,
             const float* __restrict__ pos)
{
    extern __shared__ char smem[];
    if (blockIdx.x < BATCH) {
        fps_body(pos, smem, blockIdx.x);
    } else {
        allknn_body(feats, pos, smem, blockIdx.x - BATCH);
    }
}

// ---------------------------------------------------------------------------
// Epilogue, x4-vectorized: each thread handles 4 consecutive m (within one
// (b,c) row since 2048 % 4 == 0): one int4 idx load, 4 scalar gathers (more
// MLP per thread), one STG.128. pooled[b,c,m] = allpooled[b,c, idx[b,m]];
// sampled[b,r,m] = pos[b,r, idx[b,m]] (verbatim coord copy, bit-identical).
// ---------------------------------------------------------------------------
#define POOL_ELEMS (BATCH * CHANNELS * N_SMP)      // 2,097,152
#define SMP_ELEMS  (BATCH * 3 * N_SMP)             // 49,152

__global__ void __launch_bounds__(256)
gather_kernel(const float* __restrict__ pos,
              float* __restrict__ pooled,
              float* __restrict__ sampled)
{
    int base = (blockIdx.x * 256 + threadIdx.x) * 4;
    if (base < POOL_ELEMS) {
        int m4 = base & (N_SMP - 1);
        int bc = base >> 11;                       // b*128 + c
        int b  = bc >> 7;
        int4 ii = *(const int4*)(g_idx + b * N_SMP + m4);
        const float* ap = g_allpooled + (size_t)bc * N_PTS;
        float4 out;
        out.x = __ldg(ap + ii.x);
        out.y = __ldg(ap + ii.y);
        out.z = __ldg(ap + ii.z);
        out.w = __ldg(ap + ii.w);
        *(float4*)(pooled + base) = out;
    } else {
        int sid = base - POOL_ELEMS;
        int m4 = sid & (N_SMP - 1);
        int br = sid >> 11;                        // b*3 + r
        int b  = br / 3;
        int r  = br - 3 * b;
        int4 ii = *(const int4*)(g_idx + b * N_SMP + m4);
        const float* pr = pos + ((size_t)b * 3 + r) * N_PTS;
        float4 out;
        out.x = __ldg(pr + ii.x);
        out.y = __ldg(pr + ii.y);
        out.z = __ldg(pr + ii.z);
        out.w = __ldg(pr + ii.w);
        *(float4*)(sampled + sid) = out;
    }
}

// ---------------------------------------------------------------------------
// Launch
// ---------------------------------------------------------------------------
extern "C" void kernel_launch(void* const* d_in, const int* in_sizes, int n_in,
                              void* d_out, int out_size)
{
    const float* feats = (const float*)d_in[0];   // (8,128,8192)
    const float* pos   = (const float*)d_in[1];   // (8,3,8192)

    float* pooled  = (float*)d_out;                                    // (8,128,2048)
    float* sampled = (float*)d_out + (size_t)BATCH * CHANNELS * N_SMP; // (8,3,2048)

    cudaFuncSetAttribute(fused_kernel,
                         cudaFuncAttributeMaxDynamicSharedMemorySize,
                         FUSED_SMEM_BYTES);

    const int n_ctas = BATCH + BATCH * KNN_CTAS_PER_BATCH;   // 264
    fused_kernel<<<n_ctas, 1024, FUSED_SMEM_BYTES>>>(feats, pos);

    const int tot4 = (POOL_ELEMS + SMP_ELEMS) / 4;           // 536,576
    gather_kernel<<<tot4 / 256, 256>>>(pos, pooled, sampled);
}